// round 1
// baseline (speedup 1.0000x reference)
#include <cuda_runtime.h>
#include <math_constants.h>
#include <math.h>

// Problem constants
#define B_ 4
#define L_ 1024
#define D_ 1024
#define H_ 16
#define HD_ 64
#define J_ 2048   // 2L

// Scratch (device globals -- no cudaMalloc allowed)
__device__ float g_pos[J_ * HD_];                       // 512 KB
__device__ float g_qv[(size_t)B_ * L_ * 2 * D_];        // 32 MB  (cols 0..1023 = q, 1024..2047 = v)
__device__ float g_S[(size_t)B_ * H_ * L_ * L_];        // 256 MB scores

// ---------------------------------------------------------------------------
// K1: relative sinusoidal positional table. pos row p <-> position (p - L).
// emb[p][i] = sin((p-L)*freq[i]) for i<32, cos((p-L)*freq[i-32]) for i>=32.
// Row 0 (padding_idx) zeroed.
// ---------------------------------------------------------------------------
__global__ void k_pos() {
    int p = blockIdx.x;     // 0..2047
    int i = threadIdx.x;    // 0..63
    float val = 0.0f;
    if (p != 0) {
        const float scale = logf(10000.0f) / 31.0f;
        int hi = (i < 32) ? i : (i - 32);
        float freq = expf(-scale * (float)hi);
        float ang = (float)(p - 1024) * freq;
        val = (i < 32) ? sinf(ang) : cosf(ang);
    }
    g_pos[p * HD_ + i] = val;
}

// ---------------------------------------------------------------------------
// K2: qv = x @ Wqv.   x:[4096,1024], Wqv:[1024,2048] -> g_qv:[4096,2048]
// 128x128x16 tile, 256 threads, 8x8 per thread.
// ---------------------------------------------------------------------------
__global__ __launch_bounds__(256) void k_gemm_qv(const float* __restrict__ A,
                                                 const float* __restrict__ Bm) {
    const int M = 4096, N = 2048, K = 1024;
    const int BK = 16;
    __shared__ float As[BK][128];
    __shared__ float Bs[BK][128];
    int tid = threadIdx.x;
    int brow = blockIdx.y * 128;
    int bcol = blockIdx.x * 128;
    int tx = tid & 15, ty = tid >> 4;
    float acc[8][8] = {};
    for (int k0 = 0; k0 < K; k0 += BK) {
#pragma unroll
        for (int i = 0; i < 2; i++) {
            int idx = tid * 2 + i;              // 0..511
            int r = idx >> 2;                   // 0..127
            int c4 = (idx & 3) * 4;             // 0,4,8,12
            float4 va = *(const float4*)(A + (size_t)(brow + r) * K + k0 + c4);
            As[c4 + 0][r] = va.x; As[c4 + 1][r] = va.y;
            As[c4 + 2][r] = va.z; As[c4 + 3][r] = va.w;
            int rb = idx >> 5;                  // 0..15
            int cb4 = (idx & 31) * 4;           // 0..124
            *(float4*)&Bs[rb][cb4] = *(const float4*)(Bm + (size_t)(k0 + rb) * N + bcol + cb4);
        }
        __syncthreads();
#pragma unroll
        for (int kk = 0; kk < BK; kk++) {
            float ar[8], br[8];
#pragma unroll
            for (int i = 0; i < 8; i++) ar[i] = As[kk][ty * 8 + i];
#pragma unroll
            for (int j = 0; j < 8; j++) br[j] = Bs[kk][tx * 8 + j];
#pragma unroll
            for (int i = 0; i < 8; i++)
#pragma unroll
                for (int j = 0; j < 8; j++)
                    acc[i][j] = fmaf(ar[i], br[j], acc[i][j]);
        }
        __syncthreads();
    }
#pragma unroll
    for (int i = 0; i < 8; i++)
#pragma unroll
        for (int j = 0; j < 8; j += 4) {
            float4 v = make_float4(acc[i][j], acc[i][j + 1], acc[i][j + 2], acc[i][j + 3]);
            *(float4*)(g_qv + (size_t)(brow + ty * 8 + i) * N + bcol + tx * 8 + j) = v;
        }
}

// ---------------------------------------------------------------------------
// K3: AC. Per (b,h): S[q,k] = sum_d (q[q,d] + rr[d]) * x[k,d].  M=N=1024, K=64.
// ---------------------------------------------------------------------------
__global__ __launch_bounds__(256) void k_ac(const float* __restrict__ x,
                                            const float* __restrict__ rr) {
    const int BK = 16;
    __shared__ float As[BK][128];
    __shared__ float Bs[BK][128];
    int bh = blockIdx.z;
    int b = bh >> 4, h = bh & 15;
    int brow = blockIdx.y * 128;
    int bcol = blockIdx.x * 128;
    int tid = threadIdx.x;
    int tx = tid & 15, ty = tid >> 4;
    const float* qbase = g_qv + (size_t)b * L_ * 2048 + h * 64;
    const float* xbase = x + (size_t)b * L_ * 1024 + h * 64;
    float acc[8][8] = {};
    for (int k0 = 0; k0 < 64; k0 += BK) {
#pragma unroll
        for (int i = 0; i < 2; i++) {
            int idx = tid * 2 + i;
            int r = idx >> 2;
            int c4 = (idx & 3) * 4;
            float4 va = *(const float4*)(qbase + (size_t)(brow + r) * 2048 + k0 + c4);
            float4 vb = *(const float4*)(rr + h * 64 + k0 + c4);
            As[c4 + 0][r] = va.x + vb.x; As[c4 + 1][r] = va.y + vb.y;
            As[c4 + 2][r] = va.z + vb.z; As[c4 + 3][r] = va.w + vb.w;
            float4 vk = *(const float4*)(xbase + (size_t)(bcol + r) * 1024 + k0 + c4);
            Bs[c4 + 0][r] = vk.x; Bs[c4 + 1][r] = vk.y;
            Bs[c4 + 2][r] = vk.z; Bs[c4 + 3][r] = vk.w;
        }
        __syncthreads();
#pragma unroll
        for (int kk = 0; kk < BK; kk++) {
            float ar[8], br[8];
#pragma unroll
            for (int i = 0; i < 8; i++) ar[i] = As[kk][ty * 8 + i];
#pragma unroll
            for (int j = 0; j < 8; j++) br[j] = Bs[kk][tx * 8 + j];
#pragma unroll
            for (int i = 0; i < 8; i++)
#pragma unroll
                for (int j = 0; j < 8; j++)
                    acc[i][j] = fmaf(ar[i], br[j], acc[i][j]);
        }
        __syncthreads();
    }
    float* Sb = g_S + (size_t)bh * L_ * L_;
#pragma unroll
    for (int i = 0; i < 8; i++)
#pragma unroll
        for (int j = 0; j < 8; j += 4) {
            float4 v = make_float4(acc[i][j], acc[i][j + 1], acc[i][j + 2], acc[i][j + 3]);
            *(float4*)(Sb + (size_t)(brow + ty * 8 + i) * L_ + bcol + tx * 8 + j) = v;
        }
}

// ---------------------------------------------------------------------------
// K4: relative term with fused shift. Per (b,h):
//   c[q,j] = sum_d (q[q,d] + rw[d]) * pos[j,d];  then S[q, j+q-L] += c  (if in range)
// Tiles whose diagonal band misses [0,L) are skipped (~44%).
// Mapping (q,j)->(q,k) is injective -> plain RMW is race-free (K3 ran first).
// ---------------------------------------------------------------------------
__global__ __launch_bounds__(256) void k_brel(const float* __restrict__ rw) {
    const int BK = 16;
    int bh = blockIdx.z;
    int b = bh >> 4, h = bh & 15;
    int brow = blockIdx.y * 128;   // q0
    int bcol = blockIdx.x * 128;   // j0
    // need some (q,j) with q+j in [L, 2L-1]
    if (brow + bcol > 2047 || brow + bcol + 254 < 1024) return;
    __shared__ float As[BK][128];
    __shared__ float Bs[BK][128];
    int tid = threadIdx.x;
    int tx = tid & 15, ty = tid >> 4;
    const float* qbase = g_qv + (size_t)b * L_ * 2048 + h * 64;
    float acc[8][8] = {};
    for (int k0 = 0; k0 < 64; k0 += BK) {
#pragma unroll
        for (int i = 0; i < 2; i++) {
            int idx = tid * 2 + i;
            int r = idx >> 2;
            int c4 = (idx & 3) * 4;
            float4 va = *(const float4*)(qbase + (size_t)(brow + r) * 2048 + k0 + c4);
            float4 vb = *(const float4*)(rw + h * 64 + k0 + c4);
            As[c4 + 0][r] = va.x + vb.x; As[c4 + 1][r] = va.y + vb.y;
            As[c4 + 2][r] = va.z + vb.z; As[c4 + 3][r] = va.w + vb.w;
            float4 vp = *(const float4*)(g_pos + (size_t)(bcol + r) * 64 + k0 + c4);
            Bs[c4 + 0][r] = vp.x; Bs[c4 + 1][r] = vp.y;
            Bs[c4 + 2][r] = vp.z; Bs[c4 + 3][r] = vp.w;
        }
        __syncthreads();
#pragma unroll
        for (int kk = 0; kk < BK; kk++) {
            float ar[8], br[8];
#pragma unroll
            for (int i = 0; i < 8; i++) ar[i] = As[kk][ty * 8 + i];
#pragma unroll
            for (int j = 0; j < 8; j++) br[j] = Bs[kk][tx * 8 + j];
#pragma unroll
            for (int i = 0; i < 8; i++)
#pragma unroll
                for (int j = 0; j < 8; j++)
                    acc[i][j] = fmaf(ar[i], br[j], acc[i][j]);
        }
        __syncthreads();
    }
    float* Sb = g_S + (size_t)bh * L_ * L_;
#pragma unroll
    for (int i = 0; i < 8; i++) {
        int q = brow + ty * 8 + i;
#pragma unroll
        for (int j = 0; j < 8; j++) {
            int k = bcol + tx * 8 + j + q - 1024;
            if ((unsigned)k < 1024u)
                Sb[(size_t)q * L_ + k] += acc[i][j];
        }
    }
}

// ---------------------------------------------------------------------------
// K5: masked row softmax in place. One block (256 thr) per row of 1024.
// ---------------------------------------------------------------------------
__global__ __launch_bounds__(256) void k_softmax(const int* __restrict__ mask) {
    __shared__ float red[8];
    int row = blockIdx.x;           // 0..65535
    int b = row >> 14;              // row / (H*L)
    float* S = g_S + (size_t)row * L_;
    int tid = threadIdx.x;
    float4 v = *(float4*)(S + tid * 4);
    int4 mi = *(const int4*)(mask + b * L_ + tid * 4);
    float x0 = mi.x ? v.x : -CUDART_INF_F;
    float x1 = mi.y ? v.y : -CUDART_INF_F;
    float x2 = mi.z ? v.z : -CUDART_INF_F;
    float x3 = mi.w ? v.w : -CUDART_INF_F;
    float mx = fmaxf(fmaxf(x0, x1), fmaxf(x2, x3));
#pragma unroll
    for (int o = 16; o; o >>= 1) mx = fmaxf(mx, __shfl_xor_sync(0xffffffffu, mx, o));
    if ((tid & 31) == 0) red[tid >> 5] = mx;
    __syncthreads();
    if (tid < 8) {
        float t = red[tid];
#pragma unroll
        for (int o = 4; o; o >>= 1) t = fmaxf(t, __shfl_xor_sync(0xffu, t, o));
        red[tid] = t;
    }
    __syncthreads();
    float m = red[0];
    float e0 = expf(x0 - m), e1 = expf(x1 - m), e2 = expf(x2 - m), e3 = expf(x3 - m);
    float s = e0 + e1 + e2 + e3;
#pragma unroll
    for (int o = 16; o; o >>= 1) s += __shfl_xor_sync(0xffffffffu, s, o);
    __syncthreads();    // before reusing red
    if ((tid & 31) == 0) red[tid >> 5] = s;
    __syncthreads();
    if (tid < 8) {
        float t = red[tid];
#pragma unroll
        for (int o = 4; o; o >>= 1) t += __shfl_xor_sync(0xffu, t, o);
        red[tid] = t;
    }
    __syncthreads();
    float inv = 1.0f / red[0];
    *(float4*)(S + tid * 4) = make_float4(e0 * inv, e1 * inv, e2 * inv, e3 * inv);
}

// ---------------------------------------------------------------------------
// K6: out = attn @ v per (b,h). M=1024, N=64, K=1024. 64x64x32 tile, 4x4 micro.
// Output interleaved: out[b, q, h*64 + d].
// ---------------------------------------------------------------------------
__global__ __launch_bounds__(256) void k_out(float* __restrict__ out) {
    const int BK = 32;
    __shared__ float As[BK][64];
    __shared__ float Bs[BK][64];
    int bh = blockIdx.y;
    int b = bh >> 4, h = bh & 15;
    int brow = blockIdx.x * 64;
    int tid = threadIdx.x;
    int tx = tid & 15, ty = tid >> 4;
    const float* Sb = g_S + (size_t)bh * L_ * L_;
    const float* vbase = g_qv + (size_t)b * L_ * 2048 + 1024 + h * 64;
    float acc[4][4] = {};
    for (int k0 = 0; k0 < L_; k0 += BK) {
#pragma unroll
        for (int i = 0; i < 2; i++) {
            int idx = tid * 2 + i;             // 0..511
            int r = idx >> 3;                  // 0..63 (attn row)
            int c4 = (idx & 7) * 4;            // 0..28
            float4 va = *(const float4*)(Sb + (size_t)(brow + r) * L_ + k0 + c4);
            As[c4 + 0][r] = va.x; As[c4 + 1][r] = va.y;
            As[c4 + 2][r] = va.z; As[c4 + 3][r] = va.w;
            int rb = idx >> 4;                 // 0..31 (v k-row)
            int cb4 = (idx & 15) * 4;          // 0..60
            *(float4*)&Bs[rb][cb4] = *(const float4*)(vbase + (size_t)(k0 + rb) * 2048 + cb4);
        }
        __syncthreads();
#pragma unroll
        for (int kk = 0; kk < BK; kk++) {
            float ar[4], br[4];
#pragma unroll
            for (int i = 0; i < 4; i++) ar[i] = As[kk][ty * 4 + i];
#pragma unroll
            for (int j = 0; j < 4; j++) br[j] = Bs[kk][tx * 4 + j];
#pragma unroll
            for (int i = 0; i < 4; i++)
#pragma unroll
                for (int j = 0; j < 4; j++)
                    acc[i][j] = fmaf(ar[i], br[j], acc[i][j]);
        }
        __syncthreads();
    }
#pragma unroll
    for (int i = 0; i < 4; i++) {
        float4 v = make_float4(acc[i][0], acc[i][1], acc[i][2], acc[i][3]);
        *(float4*)(out + (size_t)(b * L_ + brow + ty * 4 + i) * D_ + h * 64 + tx * 4) = v;
    }
}

// ---------------------------------------------------------------------------
extern "C" void kernel_launch(void* const* d_in, const int* in_sizes, int n_in,
                              void* d_out, int out_size) {
    (void)in_sizes; (void)n_in; (void)out_size;
    const float* x    = (const float*)d_in[0];   // [4,1024,1024]
    const float* Wqv  = (const float*)d_in[1];   // [1024,2048]
    const float* rr   = (const float*)d_in[2];   // [16,64]
    const float* rw   = (const float*)d_in[3];   // [16,64]
    const int*   mask = (const int*)d_in[4];     // [4,1024]
    float* out = (float*)d_out;                  // [4,1024,1024]

    k_pos<<<J_, HD_>>>();
    k_gemm_qv<<<dim3(16, 32), 256>>>(x, Wqv);
    k_ac<<<dim3(8, 8, 64), 256>>>(x, rr);
    k_brel<<<dim3(16, 8, 64), 256>>>(rw);
    k_softmax<<<64 * 1024, 256>>>(mask);
    k_out<<<dim3(16, 64), 256>>>(out);
}

// round 4
// speedup vs baseline: 1.1931x; 1.1931x over previous
#include <cuda_runtime.h>
#include <cuda_bf16.h>
#include <math_constants.h>
#include <math.h>
#include <cstdint>

// ---------------------------------------------------------------------------
// Problem constants: B=4, L=1024, D=1024, H=16, HD=64
// ---------------------------------------------------------------------------
#define B_ 4
#define L_ 1024
#define D_ 1024
#define H_ 16
#define HD_ 64

// ---------------------------------------------------------------------------
// Device scratch (no cudaMalloc allowed)
// ---------------------------------------------------------------------------
__device__ __align__(16) float g_pos[2048 * 64];                 // 512 KB
__device__ __align__(16) float g_E[16 * 2048];                   // (rw-rr)·pos
__device__ __align__(16) __nv_bfloat16 g_xh[4096 * 1024];        // x hi
__device__ __align__(16) __nv_bfloat16 g_xl[4096 * 1024];        // x lo
__device__ __align__(16) __nv_bfloat16 g_wh[2048 * 1024];        // Wqv^T hi  [n][k]
__device__ __align__(16) __nv_bfloat16 g_wl[2048 * 1024];        // Wqv^T lo
__device__ __align__(16) float g_u[4096 * 1024];                 // q + r_r_bias
__device__ __align__(16) float g_v[4096 * 1024];                 // v
__device__ __align__(16) float g_S[(size_t)64 * 1024 * 1024];    // 256 MB logits
__device__ __align__(16) float g_pm[65536 * 8];                  // partial row max per k-tile
__device__ __align__(16) float g_ps[65536 * 8];                  // partial row sumexp
__device__ __align__(16) float g_m[65536];                       // row max
__device__ __align__(16) float g_inv[65536];                     // 1/Z

// ---------------------------------------------------------------------------
// K1: relative sinusoidal positional table. row p <-> position (p - L).
// ---------------------------------------------------------------------------
__global__ void k_pos() {
    int p = blockIdx.x;     // 0..2047
    int i = threadIdx.x;    // 0..63
    float val = 0.0f;
    if (p != 0) {
        const float scale = logf(10000.0f) / 31.0f;
        int hi = (i < 32) ? i : (i - 32);
        float freq = expf(-scale * (float)hi);
        float ang = (float)(p - 1024) * freq;
        val = (i < 32) ? sinf(ang) : cosf(ang);
    }
    g_pos[p * HD_ + i] = val;
}

// ---------------------------------------------------------------------------
// K2a/K2b: split-precision bf16 decomposition of x and Wqv (Wqv transposed).
// ---------------------------------------------------------------------------
__global__ __launch_bounds__(256) void k_decomp_x(const float* __restrict__ x) {
    int idx = blockIdx.x * 256 + threadIdx.x;        // 0..4194303
    float f = x[idx];
    __nv_bfloat16 h = __float2bfloat16(f);
    g_xh[idx] = h;
    g_xl[idx] = __float2bfloat16(f - __bfloat162float(h));
}
__global__ __launch_bounds__(256) void k_decomp_w(const float* __restrict__ W) {
    int idx = blockIdx.x * 256 + threadIdx.x;        // 0..2097151
    int k = idx >> 11, n = idx & 2047;               // W[k][n]
    float f = W[idx];
    __nv_bfloat16 h = __float2bfloat16(f);
    g_wh[n * 1024 + k] = h;
    g_wl[n * 1024 + k] = __float2bfloat16(f - __bfloat162float(h));
}

// ---------------------------------------------------------------------------
// K3: E[h][j] = sum_d (rw - rr)[h][d] * pos[j][d]
// ---------------------------------------------------------------------------
__global__ __launch_bounds__(256) void k_E(const float* __restrict__ rr,
                                           const float* __restrict__ rw) {
    int idx = blockIdx.x * 256 + threadIdx.x;        // h*2048 + j
    int h = idx >> 11, j = idx & 2047;
    float s = 0.0f;
#pragma unroll 8
    for (int d = 0; d < 64; d++)
        s += (rw[h * 64 + d] - rr[h * 64 + d]) * g_pos[j * 64 + d];
    g_E[idx] = s;
}

// ---------------------------------------------------------------------------
// K4: qv = x @ Wqv via mma.sync m16n8k16 bf16 split (hh + hl + lh).
// 128x128 block, 8 warps in 2x4 (each 64x32). Fragments loaded directly
// from global (k-pairs are contiguous for both A[m][k] and W^T[n][k]).
// Epilogue writes u = q + rr (cols < 1024) or v (cols >= 1024).
// ---------------------------------------------------------------------------
__device__ __forceinline__ void mma_bf16(float* c, const uint32_t* a, const uint32_t* b) {
    asm volatile(
        "mma.sync.aligned.m16n8k16.row.col.f32.bf16.bf16.f32 "
        "{%0,%1,%2,%3}, {%4,%5,%6,%7}, {%8,%9}, {%0,%1,%2,%3};"
        : "+f"(c[0]), "+f"(c[1]), "+f"(c[2]), "+f"(c[3])
        : "r"(a[0]), "r"(a[1]), "r"(a[2]), "r"(a[3]), "r"(b[0]), "r"(b[1]));
}

__global__ __launch_bounds__(256) void k_qv_mma(const float* __restrict__ rr) {
    int tid = threadIdx.x, wid = tid >> 5, lane = tid & 31;
    int brow = blockIdx.y * 128;     // M tile (x rows)
    int bcol = blockIdx.x * 128;     // N tile (qv cols)
    int wm = (wid >> 2) * 64;        // warp m-offset within block
    int wn = (wid & 3) * 32;         // warp n-offset within block
    int g = lane >> 2, t = lane & 3;

    float acc[4][4][4] = {};         // [mi][ni][reg]

    // row base pointers (uint32 view; 512 uint32 per 1024-half row)
    const uint32_t* xh = (const uint32_t*)g_xh;
    const uint32_t* xl = (const uint32_t*)g_xl;
    const uint32_t* wh = (const uint32_t*)g_wh;
    const uint32_t* wl = (const uint32_t*)g_wl;

#pragma unroll 2
    for (int k0 = 0; k0 < 1024; k0 += 16) {
        int kw = k0 >> 1;            // uint32 offset of k0
        uint32_t ah[4][4], al[4][4], bh[4][2], bl[4][2];
#pragma unroll
        for (int mi = 0; mi < 4; mi++) {
            size_t r0 = (size_t)(brow + wm + mi * 16 + g) * 512 + kw + t;
            ah[mi][0] = xh[r0];            al[mi][0] = xl[r0];
            ah[mi][2] = xh[r0 + 4];        al[mi][2] = xl[r0 + 4];
            ah[mi][1] = xh[r0 + 8 * 512];  al[mi][1] = xl[r0 + 8 * 512];
            ah[mi][3] = xh[r0 + 8 * 512 + 4]; al[mi][3] = xl[r0 + 8 * 512 + 4];
        }
#pragma unroll
        for (int ni = 0; ni < 4; ni++) {
            size_t r0 = (size_t)(bcol + wn + ni * 8 + g) * 512 + kw + t;
            bh[ni][0] = wh[r0]; bh[ni][1] = wh[r0 + 4];
            bl[ni][0] = wl[r0]; bl[ni][1] = wl[r0 + 4];
        }
#pragma unroll
        for (int mi = 0; mi < 4; mi++)
#pragma unroll
            for (int ni = 0; ni < 4; ni++) {
                mma_bf16(acc[mi][ni], ah[mi], bh[ni]);
                mma_bf16(acc[mi][ni], ah[mi], bl[ni]);
                mma_bf16(acc[mi][ni], al[mi], bh[ni]);
            }
    }

    // epilogue: c0=(g,2t) c1=(g,2t+1) c2=(g+8,2t) c3=(g+8,2t+1)
    bool is_q = (bcol < 1024);
#pragma unroll
    for (int mi = 0; mi < 4; mi++) {
#pragma unroll
        for (int ni = 0; ni < 4; ni++) {
            int row0 = brow + wm + mi * 16 + g;
            int cn = bcol + wn + ni * 8 + 2 * t;
            float2 v0 = make_float2(acc[mi][ni][0], acc[mi][ni][1]);
            float2 v1 = make_float2(acc[mi][ni][2], acc[mi][ni][3]);
            if (is_q) {
                float2 rb = *(const float2*)(rr + cn);
                v0.x += rb.x; v0.y += rb.y;
                v1.x += rb.x; v1.y += rb.y;
                *(float2*)&g_u[(size_t)row0 * 1024 + cn] = v0;
                *(float2*)&g_u[(size_t)(row0 + 8) * 1024 + cn] = v1;
            } else {
                *(float2*)&g_v[(size_t)row0 * 1024 + cn - 1024] = v0;
                *(float2*)&g_v[(size_t)(row0 + 8) * 1024 + cn - 1024] = v1;
            }
        }
    }
}

// ---------------------------------------------------------------------------
// K5: fused S-writer. S[q,k] = u·x_k + u·pos[k-q+L] + E[h,k-q+L], masked,
// plus per-(row, k-tile) partial softmax stats. 128x128 tile, 8x8 micro.
// ---------------------------------------------------------------------------
__global__ __launch_bounds__(256) void k_swriter(const float* __restrict__ x,
                                                 const int* __restrict__ mask) {
    __shared__ float As[16][128];   // u tile (kk-major)
    __shared__ float Bs[16][128];   // x-key tile
    __shared__ float Ps[16][256];   // pos band (255 rows used)
    __shared__ float Es[256];       // E band
    __shared__ int   msk[128];
    int bh = blockIdx.z, b = bh >> 4, h = bh & 15;
    int brow = blockIdx.y * 128;    // q tile
    int bcol = blockIdx.x * 128;    // k tile
    int jbase = bcol - brow + 897;  // in [1,1793]
    int tid = threadIdx.x, tx = tid & 15, ty = tid >> 4;

    if (tid < 255) Es[tid] = g_E[h * 2048 + jbase + tid];
    if (tid < 128) msk[tid] = mask[b * 1024 + bcol + tid];

    const float* ub = g_u + (size_t)(b * 1024 + brow) * 1024 + h * 64;
    const float* xb = x   + (size_t)(b * 1024 + bcol) * 1024 + h * 64;

    float acc[8][8] = {};
    for (int k0 = 0; k0 < 64; k0 += 16) {
#pragma unroll
        for (int i = 0; i < 2; i++) {
            int idx = tid * 2 + i;              // 0..511
            int r = idx >> 2;                   // 0..127
            int c4 = (idx & 3) * 4;
            float4 va = *(const float4*)(ub + (size_t)r * 1024 + k0 + c4);
            As[c4 + 0][r] = va.x; As[c4 + 1][r] = va.y;
            As[c4 + 2][r] = va.z; As[c4 + 3][r] = va.w;
            float4 vk = *(const float4*)(xb + (size_t)r * 1024 + k0 + c4);
            Bs[c4 + 0][r] = vk.x; Bs[c4 + 1][r] = vk.y;
            Bs[c4 + 2][r] = vk.z; Bs[c4 + 3][r] = vk.w;
        }
        if (tid < 255) {
            const float* pp = g_pos + (size_t)(jbase + tid) * 64 + k0;
#pragma unroll
            for (int ii = 0; ii < 4; ii++) {
                float4 vp = *(const float4*)(pp + ii * 4);
                Ps[ii * 4 + 0][tid] = vp.x; Ps[ii * 4 + 1][tid] = vp.y;
                Ps[ii * 4 + 2][tid] = vp.z; Ps[ii * 4 + 3][tid] = vp.w;
            }
        }
        __syncthreads();
        int pb = tx * 8 - ty * 8 + 120;
#pragma unroll
        for (int kk = 0; kk < 16; kk++) {
            float ar[8], br[8], pr[15];
#pragma unroll
            for (int i = 0; i < 8; i++) ar[i] = As[kk][ty * 8 + i];
#pragma unroll
            for (int j = 0; j < 8; j++) br[j] = Bs[kk][tx * 8 + j];
#pragma unroll
            for (int t = 0; t < 15; t++) pr[t] = Ps[kk][pb + t];
#pragma unroll
            for (int i = 0; i < 8; i++) {
                float a = ar[i];
#pragma unroll
                for (int j = 0; j < 8; j++) {
                    acc[i][j] = fmaf(a, br[j], acc[i][j]);
                    acc[i][j] = fmaf(a, pr[j - i + 7], acc[i][j]);
                }
            }
        }
        __syncthreads();
    }

    // epilogue: add E band, mask, write S, emit partial row stats
    float* Sb = g_S + (size_t)bh * 1024 * 1024;
#pragma unroll
    for (int i = 0; i < 8; i++) {
        int lq = ty * 8 + i;
        float vals[8];
        float vmax = -CUDART_INF_F;
#pragma unroll
        for (int j = 0; j < 8; j++) {
            int lk = tx * 8 + j;
            float v = acc[i][j] + Es[lk - lq + 127];
            if (msk[lk] == 0) v = -CUDART_INF_F;
            vals[j] = v;
            vmax = fmaxf(vmax, v);
        }
#pragma unroll
        for (int o = 8; o; o >>= 1) vmax = fmaxf(vmax, __shfl_xor_sync(0xffffffffu, vmax, o));
        float ssum = 0.0f;
#pragma unroll
        for (int j = 0; j < 8; j++) {
            float e = (vals[j] == -CUDART_INF_F) ? 0.0f : __expf(vals[j] - vmax);
            ssum += e;
        }
#pragma unroll
        for (int o = 8; o; o >>= 1) ssum += __shfl_xor_sync(0xffffffffu, ssum, o);

        float* row = Sb + (size_t)(brow + lq) * 1024 + bcol + tx * 8;
        *(float4*)(row)     = make_float4(vals[0], vals[1], vals[2], vals[3]);
        *(float4*)(row + 4) = make_float4(vals[4], vals[5], vals[6], vals[7]);
        if (tx == 0) {
            size_t sidx = ((size_t)bh * 1024 + brow + lq) * 8 + blockIdx.x;
            g_pm[sidx] = vmax;
            g_ps[sidx] = ssum;
        }
    }
}

// ---------------------------------------------------------------------------
// K6: combine partial softmax stats -> row max + 1/Z
// ---------------------------------------------------------------------------
__global__ __launch_bounds__(256) void k_combine() {
    int r = blockIdx.x * 256 + threadIdx.x;  // 0..65535
    float m = -CUDART_INF_F;
#pragma unroll
    for (int t = 0; t < 8; t++) m = fmaxf(m, g_pm[r * 8 + t]);
    float z = 0.0f;
#pragma unroll
    for (int t = 0; t < 8; t++) {
        float s = g_ps[r * 8 + t];
        if (s > 0.0f) z += s * __expf(g_pm[r * 8 + t] - m);
    }
    g_m[r] = m;
    g_inv[r] = 1.0f / z;
}

// ---------------------------------------------------------------------------
// K7: PV with fused softmax. out = softmax(S) @ v per (b,h).
// 128x64 tile, K loop 1024 step 16, 8x4 micro.  Grid: (8 q-tiles, 64 bh).
// ---------------------------------------------------------------------------
__global__ __launch_bounds__(256) void k_pv(float* __restrict__ out) {
    const int BK = 16;
    __shared__ float As[BK][128];
    __shared__ float Bs[BK][64];
    __shared__ float ms[128], invs[128];
    int bh = blockIdx.y;
    int b = bh >> 4, h = bh & 15;
    int brow = blockIdx.x * 128;
    int tid = threadIdx.x;
    int tx = tid & 15, ty = tid >> 4;
    const float* Sb = g_S + (size_t)bh * 1024 * 1024;
    const float* vbase = g_v + (size_t)(b * 1024) * 1024 + h * 64;

    if (tid < 128) {
        int rg = bh * 1024 + brow + tid;
        ms[tid] = g_m[rg];
        invs[tid] = g_inv[rg];
    }
    __syncthreads();

    float acc[8][4] = {};
    for (int k0 = 0; k0 < 1024; k0 += BK) {
#pragma unroll
        for (int i = 0; i < 2; i++) {
            int idx = tid * 2 + i;             // 0..511
            int r = idx >> 2;                  // 0..127 attn row
            int c4 = (idx & 3) * 4;            // 0..12
            float4 va = *(const float4*)(Sb + (size_t)(brow + r) * 1024 + k0 + c4);
            float mr = ms[r], ir = invs[r];
            As[c4 + 0][r] = __expf(va.x - mr) * ir;
            As[c4 + 1][r] = __expf(va.y - mr) * ir;
            As[c4 + 2][r] = __expf(va.z - mr) * ir;
            As[c4 + 3][r] = __expf(va.w - mr) * ir;
        }
        {
            int rb = tid >> 4;                 // 0..15 v k-row
            int cb4 = (tid & 15) * 4;          // 0..60
            *(float4*)&Bs[rb][cb4] = *(const float4*)(vbase + (size_t)(k0 + rb) * 1024 + cb4);
        }
        __syncthreads();
#pragma unroll
        for (int kk = 0; kk < BK; kk++) {
            float ar[8], br[4];
#pragma unroll
            for (int i = 0; i < 8; i++) ar[i] = As[kk][ty * 8 + i];
#pragma unroll
            for (int j = 0; j < 4; j++) br[j] = Bs[kk][tx * 4 + j];
#pragma unroll
            for (int i = 0; i < 8; i++)
#pragma unroll
                for (int j = 0; j < 4; j++)
                    acc[i][j] = fmaf(ar[i], br[j], acc[i][j]);
        }
        __syncthreads();
    }
#pragma unroll
    for (int i = 0; i < 8; i++) {
        float4 v = make_float4(acc[i][0], acc[i][1], acc[i][2], acc[i][3]);
        *(float4*)(out + (size_t)(b * 1024 + brow + ty * 8 + i) * 1024 + h * 64 + tx * 4) = v;
    }
}

// ---------------------------------------------------------------------------
extern "C" void kernel_launch(void* const* d_in, const int* in_sizes, int n_in,
                              void* d_out, int out_size) {
    (void)in_sizes; (void)n_in; (void)out_size;
    const float* x    = (const float*)d_in[0];   // [4,1024,1024]
    const float* Wqv  = (const float*)d_in[1];   // [1024,2048]
    const float* rr   = (const float*)d_in[2];   // [16,64]
    const float* rw   = (const float*)d_in[3];   // [16,64]
    const int*   mask = (const int*)d_in[4];     // [4,1024]
    float* out = (float*)d_out;                  // [4,1024,1024]

    k_pos<<<2048, 64>>>();
    k_decomp_x<<<16384, 256>>>(x);
    k_decomp_w<<<8192, 256>>>(Wqv);
    k_E<<<128, 256>>>(rr, rw);
    k_qv_mma<<<dim3(16, 32), 256>>>(rr);
    k_swriter<<<dim3(8, 8, 64), 256>>>(x, mask);
    k_combine<<<256, 256>>>();
    k_pv<<<dim3(8, 64), 256>>>(out);     // FIX: 8 q-tiles of 128 rows (was 16 -> OOB)
}